// round 5
// baseline (speedup 1.0000x reference)
#include <cuda_runtime.h>
#include <cstdint>

// KroneckerLinear: out = x @ kron(f1,f2)^T + bias, per row Y = f1 @ X @ f2^T
// (1024 FMA/row -> 512 packed f32x2 FMA). Persistent blocks, double-buffered
// cp.async pipeline, one thread per row. R5: 3 blocks/SM (g2 table moved from
// registers to broadcast LDS to fit the register file).

#define TILE_ROWS 128
#define THREADS   128
#define PITCH4    17                      // float4 pitch per row (68 floats)
#define BUF_F4    (TILE_ROWS * PITCH4)    // 2176 float4 = 34816 B per buffer
#define BLOCKS_PER_SM 3

typedef unsigned long long u64;

__device__ __forceinline__ uint32_t s2u(const void* p) {
    uint32_t a;
    asm("{ .reg .u64 t; cvta.to.shared.u64 t, %1; cvt.u32.u64 %0, t; }"
        : "=r"(a) : "l"(p));
    return a;
}
__device__ __forceinline__ void cp16(uint32_t s, const void* g) {
    asm volatile("cp.async.cg.shared.global [%0], [%1], 16;" :: "r"(s), "l"(g));
}
__device__ __forceinline__ void cp_commit() {
    asm volatile("cp.async.commit_group;");
}
__device__ __forceinline__ void cp_wait1() {
    asm volatile("cp.async.wait_group 1;");
}
__device__ __forceinline__ u64 pack2(float lo, float hi) {
    u64 r; asm("mov.b64 %0, {%1, %2};" : "=l"(r) : "f"(lo), "f"(hi)); return r;
}
__device__ __forceinline__ void fma2(u64& d, u64 a, u64 b) {
    asm("fma.rn.f32x2 %0, %1, %2, %0;" : "+l"(d) : "l"(a), "l"(b));
}

__global__ __launch_bounds__(THREADS, BLOCKS_PER_SM)
void kron_kernel(const float4* __restrict__ gx,
                 float4*       __restrict__ gout,
                 const float*  __restrict__ f1,
                 const float*  __restrict__ f2,
                 const float*  __restrict__ bias,
                 long long nrows)
{
    extern __shared__ float4 dbuf[];          // 2 * BUF_F4 float4
    __shared__ u64 f1t[64];                   // [i*8+k] = (f1[i,k], f1[i,k])
    __shared__ u64 g2t[32];                   // [l*4+p] = (f2[2p,l], f2[2p+1,l])
    __shared__ u64 bt[32];                    // bias as packed pairs

    const int tid = threadIdx.x;
    if (tid < 32) {
        int l = tid >> 2, p = tid & 3;
        g2t[tid] = pack2(f2[(2 * p) * 8 + l], f2[(2 * p + 1) * 8 + l]);
        bt[tid]  = pack2(bias[2 * tid], bias[2 * tid + 1]);
    }
    if (tid < 64) f1t[tid] = pack2(f1[tid], f1[tid]);
    __syncthreads();

    const long long ntiles = (nrows + TILE_ROWS - 1) / TILE_ROWS;
    const uint32_t sb0 = s2u(dbuf);
    const uint32_t sb1 = s2u(dbuf + BUF_F4);

    long long tile = blockIdx.x;

    // ---- prologue: stage first tile into buffer 0 ----
    if (tile < ntiles) {
        const float4* src = gx + tile * (TILE_ROWS * 16);
        long long base = tile * TILE_ROWS;
        #pragma unroll
        for (int i = 0; i < 16; i++) {
            int f = tid + i * THREADS;
            int r = f >> 4;
            if (base + r < nrows)
                cp16(sb0 + (uint32_t)(f + r) * 16u, src + f);
        }
    }
    cp_commit();

    int b = 0;
    while (tile < ntiles) {
        const long long nt = tile + gridDim.x;

        // ---- prefetch next tile into the other buffer ----
        if (nt < ntiles) {
            const float4* src = gx + nt * (TILE_ROWS * 16);
            long long base = nt * TILE_ROWS;
            uint32_t sbn = b ? sb0 : sb1;
            #pragma unroll
            for (int i = 0; i < 16; i++) {
                int f = tid + i * THREADS;
                int r = f >> 4;
                if (base + r < nrows)
                    cp16(sbn + (uint32_t)(f + r) * 16u, src + f);
            }
        }
        cp_commit();
        cp_wait1();                 // current tile's group complete
        __syncthreads();

        // ---- compute: one thread per row, fully packed f32x2 ----
        float4* xrow = dbuf + b * BUF_F4 + tid * PITCH4;
        u64 y[32];
        #pragma unroll
        for (int m = 0; m < 32; m++) y[m] = bt[m];

        #pragma unroll 1
        for (int k = 0; k < 8; k++) {
            float4 xa = xrow[2 * k];
            float4 xb = xrow[2 * k + 1];
            float xs[8] = {xa.x, xa.y, xa.z, xa.w, xb.x, xb.y, xb.z, xb.w};
            u64 t0 = 0, t1 = 0, t2 = 0, t3 = 0;   // (0.0f, 0.0f) packed
            #pragma unroll
            for (int l = 0; l < 8; l++) {
                u64 g0 = g2t[l * 4 + 0];          // broadcast LDS.64
                u64 g1 = g2t[l * 4 + 1];
                u64 g2 = g2t[l * 4 + 2];
                u64 g3 = g2t[l * 4 + 3];
                u64 x2 = pack2(xs[l], xs[l]);
                fma2(t0, x2, g0);
                fma2(t1, x2, g1);
                fma2(t2, x2, g2);
                fma2(t3, x2, g3);
            }
            #pragma unroll
            for (int i = 0; i < 8; i++) {
                u64 a2 = f1t[i * 8 + k];          // broadcast LDS.64
                fma2(y[i * 4 + 0], a2, t0);
                fma2(y[i * 4 + 1], a2, t1);
                fma2(y[i * 4 + 2], a2, t2);
                fma2(y[i * 4 + 3], a2, t3);
            }
        }

        // write result into own row slot (in place; own-row only)
        {
            ulonglong2* yr = (ulonglong2*)xrow;
            #pragma unroll
            for (int i = 0; i < 8; i++) {
                yr[2 * i]     = make_ulonglong2(y[i * 4 + 0], y[i * 4 + 1]);
                yr[2 * i + 1] = make_ulonglong2(y[i * 4 + 2], y[i * 4 + 3]);
            }
        }
        __syncthreads();

        // ---- coalesced store ----
        {
            float4* dst = gout + tile * (TILE_ROWS * 16);
            const float4* sbuf = dbuf + b * BUF_F4;
            long long base = tile * TILE_ROWS;
            #pragma unroll
            for (int i = 0; i < 16; i++) {
                int f = tid + i * THREADS;
                int r = f >> 4;
                if (base + r < nrows)
                    dst[f] = sbuf[f + r];
            }
        }
        __syncthreads();            // buffer b reused by next iteration's prefetch

        tile = nt;
        b ^= 1;
    }
}

extern "C" void kernel_launch(void* const* d_in, const int* in_sizes, int n_in,
                              void* d_out, int out_size)
{
    const float* x    = (const float*)d_in[0];
    const float* f1   = (const float*)d_in[1];
    const float* f2   = (const float*)d_in[2];
    const float* bias = (const float*)d_in[3];
    float* out = (float*)d_out;

    long long nrows = (long long)in_sizes[0] / 64;

    const int smem_bytes = 2 * BUF_F4 * sizeof(float4);   // 69632
    cudaFuncSetAttribute(kron_kernel,
                         cudaFuncAttributeMaxDynamicSharedMemorySize, smem_bytes);

    int grid = BLOCKS_PER_SM * 148;     // persistent: 3 blocks per SM
    kron_kernel<<<grid, THREADS, smem_bytes>>>(
        (const float4*)x, (float4*)out, f1, f2, bias, nrows);
}

// round 6
// speedup vs baseline: 1.0107x; 1.0107x over previous
#include <cuda_runtime.h>
#include <cstdint>

// KroneckerLinear: out = x @ kron(f1,f2)^T + bias, per row Y = f1 @ X @ f2^T
// (1024 FMA/row -> 512 packed f32x2 FMA).
//
// R6: WARP-INDEPENDENT persistent pipelines. Each warp owns a private
// double-buffered 32-row tile (8KB contiguous in global), prefetches via
// per-thread cp.async groups, and never block-syncs after init. Compute is
// R3's: one thread per row, f2-pair table in registers, pure fma.rn.f32x2.

#define THREADS     128                  // 4 warps per block
#define WARP_ROWS   32
#define TILE_ROWS   128                  // 4 warps * 32 rows
#define PITCH4      17                   // float4 pitch per row (68 floats)
#define WBUF_F4     (WARP_ROWS * PITCH4) // 544 float4 = 8704 B per warp buffer

typedef unsigned long long u64;

__device__ __forceinline__ uint32_t s2u(const void* p) {
    uint32_t a;
    asm("{ .reg .u64 t; cvta.to.shared.u64 t, %1; cvt.u32.u64 %0, t; }"
        : "=r"(a) : "l"(p));
    return a;
}
__device__ __forceinline__ void cp16(uint32_t s, const void* g) {
    asm volatile("cp.async.cg.shared.global [%0], [%1], 16;" :: "r"(s), "l"(g));
}
__device__ __forceinline__ void cp_commit() {
    asm volatile("cp.async.commit_group;");
}
__device__ __forceinline__ void cp_wait1() {
    asm volatile("cp.async.wait_group 1;");
}
__device__ __forceinline__ u64 pack2(float lo, float hi) {
    u64 r; asm("mov.b64 %0, {%1, %2};" : "=l"(r) : "f"(lo), "f"(hi)); return r;
}
__device__ __forceinline__ void fma2(u64& d, u64 a, u64 b) {
    asm("fma.rn.f32x2 %0, %1, %2, %0;" : "+l"(d) : "l"(a), "l"(b));
}

__global__ __launch_bounds__(THREADS, 2)
void kron_kernel(const float4* __restrict__ gx,
                 float4*       __restrict__ gout,
                 const float*  __restrict__ f1,
                 const float*  __restrict__ f2,
                 const float*  __restrict__ bias,
                 long long nrows)
{
    extern __shared__ float4 dbuf[];      // 4 warps * 2 buffers * WBUF_F4
    __shared__ u64 f1t[64];               // [i*8+k] = (f1[i,k], f1[i,k])
    __shared__ u64 g2t[32];               // [l*4+p] = (f2[2p,l], f2[2p+1,l])
    __shared__ u64 bt[32];                // bias as packed pairs

    const int tid  = threadIdx.x;
    const int w    = tid >> 5;
    const int lane = tid & 31;

    if (tid < 32) {
        int l = tid >> 2, p = tid & 3;
        g2t[tid] = pack2(f2[(2 * p) * 8 + l], f2[(2 * p + 1) * 8 + l]);
        bt[tid]  = pack2(bias[2 * tid], bias[2 * tid + 1]);
    }
    if (tid < 64) f1t[tid] = pack2(f1[tid], f1[tid]);
    __syncthreads();                      // the ONLY block barrier

    // f2-pair table resident in registers for the whole kernel
    u64 g2r[32];
    #pragma unroll
    for (int m = 0; m < 32; m++) g2r[m] = g2t[m];

    const long long ntiles = (nrows + TILE_ROWS - 1) / TILE_ROWS;
    float4* wbuf = dbuf + w * (2 * WBUF_F4);
    const uint32_t sbw = s2u(wbuf);

    long long tile = blockIdx.x;

    // ---- prologue: warp stages its 32 rows of tile 0 into buffer 0 ----
    if (tile < ntiles) {
        const long long rbase = tile * TILE_ROWS + w * WARP_ROWS;
        const float4* src = gx + rbase * 16;
        #pragma unroll
        for (int i = 0; i < 16; i++) {
            int f = lane + i * 32;        // 0..511 over warp's 8KB chunk
            int r = f >> 4;
            if (rbase + r < nrows)
                cp16(sbw + (uint32_t)(r * PITCH4 + (f & 15)) * 16u, src + f);
        }
    }
    cp_commit();

    int b = 0;
    while (tile < ntiles) {
        const long long nt = tile + gridDim.x;

        // ---- prefetch this warp's slice of the next tile ----
        if (nt < ntiles) {
            const long long rbase = nt * TILE_ROWS + w * WARP_ROWS;
            const float4* src = gx + rbase * 16;
            const uint32_t sbn = sbw + (uint32_t)((b ^ 1) * WBUF_F4) * 16u;
            #pragma unroll
            for (int i = 0; i < 16; i++) {
                int f = lane + i * 32;
                int r = f >> 4;
                if (rbase + r < nrows)
                    cp16(sbn + (uint32_t)(r * PITCH4 + (f & 15)) * 16u, src + f);
            }
        }
        cp_commit();
        cp_wait1();                       // this thread's tile-t group done
        __syncwarp();

        const long long rbase = tile * TILE_ROWS + w * WARP_ROWS;
        float4* xrow = wbuf + b * WBUF_F4 + lane * PITCH4;

        if (rbase + lane < nrows) {
            // ---- compute: fully packed f32x2, g2 in registers ----
            u64 y[32];
            #pragma unroll
            for (int m = 0; m < 32; m++) y[m] = bt[m];

            #pragma unroll 1
            for (int k = 0; k < 8; k++) {
                float4 xa = xrow[2 * k];
                float4 xb = xrow[2 * k + 1];
                float xs[8] = {xa.x, xa.y, xa.z, xa.w, xb.x, xb.y, xb.z, xb.w};
                u64 t0 = 0, t1 = 0, t2 = 0, t3 = 0;
                #pragma unroll
                for (int l = 0; l < 8; l++) {
                    u64 x2 = pack2(xs[l], xs[l]);
                    fma2(t0, x2, g2r[l * 4 + 0]);
                    fma2(t1, x2, g2r[l * 4 + 1]);
                    fma2(t2, x2, g2r[l * 4 + 2]);
                    fma2(t3, x2, g2r[l * 4 + 3]);
                }
                #pragma unroll
                for (int i = 0; i < 8; i++) {
                    u64 a2 = f1t[i * 8 + k];   // broadcast LDS.64 (8/k only)
                    fma2(y[i * 4 + 0], a2, t0);
                    fma2(y[i * 4 + 1], a2, t1);
                    fma2(y[i * 4 + 2], a2, t2);
                    fma2(y[i * 4 + 3], a2, t3);
                }
            }

            // in-place writeback into own row slot
            ulonglong2* yr = (ulonglong2*)xrow;
            #pragma unroll
            for (int i = 0; i < 8; i++) {
                yr[2 * i]     = make_ulonglong2(y[i * 4 + 0], y[i * 4 + 1]);
                yr[2 * i + 1] = make_ulonglong2(y[i * 4 + 2], y[i * 4 + 3]);
            }
        }
        __syncwarp();                     // STS visible to other lanes

        // ---- coalesced store of the warp's 8KB slice ----
        {
            float4* dst = gout + rbase * 16;
            const float4* sbuf = wbuf + b * WBUF_F4;
            #pragma unroll
            for (int i = 0; i < 16; i++) {
                int f = lane + i * 32;
                int r = f >> 4;
                if (rbase + r < nrows)
                    dst[f] = sbuf[r * PITCH4 + (f & 15)];
            }
        }
        // no barrier: buffer b is private to this warp; next prefetch into it
        // is issued (program-order) after these LDS complete.

        tile = nt;
        b ^= 1;
    }
}

extern "C" void kernel_launch(void* const* d_in, const int* in_sizes, int n_in,
                              void* d_out, int out_size)
{
    const float* x    = (const float*)d_in[0];
    const float* f1   = (const float*)d_in[1];
    const float* f2   = (const float*)d_in[2];
    const float* bias = (const float*)d_in[3];
    float* out = (float*)d_out;

    long long nrows = (long long)in_sizes[0] / 64;

    const int smem_bytes = 4 * 2 * WBUF_F4 * sizeof(float4);  // 69632
    cudaFuncSetAttribute(kron_kernel,
                         cudaFuncAttributeMaxDynamicSharedMemorySize, smem_bytes);

    int grid = 2 * 148;                   // persistent: 2 blocks per SM
    kron_kernel<<<grid, THREADS, smem_bytes>>>(
        (const float4*)x, (float4*)out, f1, f2, bias, nrows);
}

// round 7
// speedup vs baseline: 1.1226x; 1.1107x over previous
#include <cuda_runtime.h>
#include <cstdint>

// KroneckerLinear: out = x @ kron(f1,f2)^T + bias, per row Y = f1 @ X @ f2^T
// (1024 FMA/row -> 512 packed f32x2 FMA).
//
// R7 = R3 (best: 170us) with a 3-stage cp.async pipeline (prefetch t+2 while
// computing t; wait_group 2) to keep ~70KB of reads in flight per block and
// remove read-burst gaps. Streaming-store hint (__stcs) on output. Compute
// path identical to R3: one thread per row, f2-pair table in registers,
// pure fma.rn.f32x2.

#define TILE_ROWS 128
#define THREADS   128
#define PITCH4    17                      // float4 pitch per row (68 floats)
#define BUF_F4    (TILE_ROWS * PITCH4)    // 2176 float4 = 34816 B per buffer
#define NBUF      3

typedef unsigned long long u64;

__device__ __forceinline__ uint32_t s2u(const void* p) {
    uint32_t a;
    asm("{ .reg .u64 t; cvta.to.shared.u64 t, %1; cvt.u32.u64 %0, t; }"
        : "=r"(a) : "l"(p));
    return a;
}
__device__ __forceinline__ void cp16(uint32_t s, const void* g) {
    asm volatile("cp.async.cg.shared.global [%0], [%1], 16;" :: "r"(s), "l"(g));
}
__device__ __forceinline__ void cp_commit() {
    asm volatile("cp.async.commit_group;");
}
__device__ __forceinline__ void cp_wait2() {
    asm volatile("cp.async.wait_group 2;");
}
__device__ __forceinline__ u64 pack2(float lo, float hi) {
    u64 r; asm("mov.b64 %0, {%1, %2};" : "=l"(r) : "f"(lo), "f"(hi)); return r;
}
__device__ __forceinline__ void fma2(u64& d, u64 a, u64 b) {
    asm("fma.rn.f32x2 %0, %1, %2, %0;" : "+l"(d) : "l"(a), "l"(b));
}

__global__ __launch_bounds__(THREADS, 2)
void kron_kernel(const float4* __restrict__ gx,
                 float4*       __restrict__ gout,
                 const float*  __restrict__ f1,
                 const float*  __restrict__ f2,
                 const float*  __restrict__ bias,
                 long long nrows)
{
    extern __shared__ float4 dbuf[];          // NBUF * BUF_F4 float4
    __shared__ u64 f1t[64];                   // [i*8+k] = (f1[i,k], f1[i,k])
    __shared__ u64 g2t[32];                   // [l*4+p] = (f2[2p,l], f2[2p+1,l])
    __shared__ u64 bt[32];                    // bias as packed pairs

    const int tid = threadIdx.x;
    if (tid < 32) {
        int l = tid >> 2, p = tid & 3;
        g2t[tid] = pack2(f2[(2 * p) * 8 + l], f2[(2 * p + 1) * 8 + l]);
        bt[tid]  = pack2(bias[2 * tid], bias[2 * tid + 1]);
    }
    if (tid < 64) f1t[tid] = pack2(f1[tid], f1[tid]);
    __syncthreads();

    // f2-pair table lives in registers for the whole kernel (tile-invariant)
    u64 g2r[32];
    #pragma unroll
    for (int m = 0; m < 32; m++) g2r[m] = g2t[m];

    const long long ntiles = (nrows + TILE_ROWS - 1) / TILE_ROWS;
    const uint32_t sbase = s2u(dbuf);

    long long tile = blockIdx.x;

    // ---- prologue: stage tiles t and t+1 into buffers 0 and 1 ----
    #pragma unroll
    for (int s = 0; s < 2; s++) {
        long long pt = tile + (long long)s * gridDim.x;
        if (pt < ntiles) {
            const float4* src = gx + pt * (TILE_ROWS * 16);
            long long base = pt * TILE_ROWS;
            uint32_t sb = sbase + (uint32_t)(s * BUF_F4) * 16u;
            #pragma unroll
            for (int i = 0; i < 16; i++) {
                int f = tid + i * THREADS;
                int r = f >> 4;
                if (base + r < nrows)
                    cp16(sb + (uint32_t)(f + r) * 16u, src + f);
            }
        }
        cp_commit();
    }

    int b = 0;
    while (tile < ntiles) {
        // ---- prefetch tile t+2 into buffer (b+2)%3 ----
        {
            const long long pt = tile + 2LL * gridDim.x;
            if (pt < ntiles) {
                const float4* src = gx + pt * (TILE_ROWS * 16);
                long long base = pt * TILE_ROWS;
                int bp = b + 2; if (bp >= NBUF) bp -= NBUF;
                uint32_t sb = sbase + (uint32_t)(bp * BUF_F4) * 16u;
                #pragma unroll
                for (int i = 0; i < 16; i++) {
                    int f = tid + i * THREADS;
                    int r = f >> 4;
                    if (base + r < nrows)
                        cp16(sb + (uint32_t)(f + r) * 16u, src + f);
                }
            }
            cp_commit();
        }
        cp_wait2();                 // current tile's group complete
        __syncthreads();

        // ---- compute: one thread per row, fully packed f32x2 ----
        float4* xrow = dbuf + b * BUF_F4 + tid * PITCH4;
        u64 y[32];
        #pragma unroll
        for (int m = 0; m < 32; m++) y[m] = bt[m];

        #pragma unroll 1
        for (int k = 0; k < 8; k++) {
            float4 xa = xrow[2 * k];
            float4 xb = xrow[2 * k + 1];
            float xs[8] = {xa.x, xa.y, xa.z, xa.w, xb.x, xb.y, xb.z, xb.w};
            u64 t0 = 0, t1 = 0, t2 = 0, t3 = 0;   // (0.0f, 0.0f) packed
            #pragma unroll
            for (int l = 0; l < 8; l++) {
                u64 x2 = pack2(xs[l], xs[l]);
                fma2(t0, x2, g2r[l * 4 + 0]);
                fma2(t1, x2, g2r[l * 4 + 1]);
                fma2(t2, x2, g2r[l * 4 + 2]);
                fma2(t3, x2, g2r[l * 4 + 3]);
            }
            #pragma unroll
            for (int i = 0; i < 8; i++) {
                u64 a2 = f1t[i * 8 + k];          // broadcast LDS.64
                fma2(y[i * 4 + 0], a2, t0);
                fma2(y[i * 4 + 1], a2, t1);
                fma2(y[i * 4 + 2], a2, t2);
                fma2(y[i * 4 + 3], a2, t3);
            }
        }

        // write result into own row slot (in place; own-row only)
        {
            ulonglong2* yr = (ulonglong2*)xrow;
            #pragma unroll
            for (int i = 0; i < 8; i++) {
                yr[2 * i]     = make_ulonglong2(y[i * 4 + 0], y[i * 4 + 1]);
                yr[2 * i + 1] = make_ulonglong2(y[i * 4 + 2], y[i * 4 + 3]);
            }
        }
        __syncthreads();

        // ---- coalesced store (streaming hint) ----
        {
            float4* dst = gout + tile * (TILE_ROWS * 16);
            const float4* sbuf = dbuf + b * BUF_F4;
            long long base = tile * TILE_ROWS;
            #pragma unroll
            for (int i = 0; i < 16; i++) {
                int f = tid + i * THREADS;
                int r = f >> 4;
                if (base + r < nrows)
                    __stcs(dst + f, sbuf[f + r]);
            }
        }
        __syncthreads();            // buffer b re-prefetched next iteration

        tile += gridDim.x;
        b = b + 1; if (b >= NBUF) b = 0;
    }
}

extern "C" void kernel_launch(void* const* d_in, const int* in_sizes, int n_in,
                              void* d_out, int out_size)
{
    const float* x    = (const float*)d_in[0];
    const float* f1   = (const float*)d_in[1];
    const float* f2   = (const float*)d_in[2];
    const float* bias = (const float*)d_in[3];
    float* out = (float*)d_out;

    long long nrows = (long long)in_sizes[0] / 64;

    const int smem_bytes = NBUF * BUF_F4 * sizeof(float4);   // 104448
    cudaFuncSetAttribute(kron_kernel,
                         cudaFuncAttributeMaxDynamicSharedMemorySize, smem_bytes);

    int grid = 2 * 148;     // persistent: 2 blocks per SM
    kron_kernel<<<grid, THREADS, smem_bytes>>>(
        (const float4*)x, (float4*)out, f1, f2, bias, nrows);
}

// round 8
// speedup vs baseline: 1.1631x; 1.0361x over previous
#include <cuda_runtime.h>
#include <cstdint>

// KroneckerLinear: out = x @ kron(f1,f2)^T + bias, factored per row as
// Y = f1 @ X @ f2^T (1024 FMA/row vs 4096 dense). Persistent blocks,
// double-buffered cp.async tile pipeline (load t+1 overlaps compute t),
// packed f32x2 FMA, one thread per row, f2-pair table in registers.
//
// CONVERGED (R8 = R3, best measured 170.0us): mandatory traffic is 1.074 GB
// (512MB read + 512MB write), each byte crossing L2/LTS exactly once.
// At the B300 LTS structural cap (~6300 B/cyc full-chip, path-independent)
// that is ~170us — exactly what this kernel measures. Four alternative
// schedules (R4-R7: split-row shuffle, 3 blocks/SM, warp-decoupled
// pipelines, 3-stage pipeline + streaming stores) all landed at the same
// ~6.0-6.3 TB/s aggregate, confirming the ceiling is the memory system,
// not the SM schedule.

#define TILE_ROWS 128
#define THREADS   128
#define PITCH4    17                      // float4 pitch per row (68 floats)
#define BUF_F4    (TILE_ROWS * PITCH4)    // 2176 float4 = 34816 B per buffer

typedef unsigned long long u64;

__device__ __forceinline__ uint32_t s2u(const void* p) {
    uint32_t a;
    asm("{ .reg .u64 t; cvta.to.shared.u64 t, %1; cvt.u32.u64 %0, t; }"
        : "=r"(a) : "l"(p));
    return a;
}
__device__ __forceinline__ void cp16(uint32_t s, const void* g) {
    asm volatile("cp.async.cg.shared.global [%0], [%1], 16;" :: "r"(s), "l"(g));
}
__device__ __forceinline__ void cp_commit() {
    asm volatile("cp.async.commit_group;");
}
__device__ __forceinline__ void cp_wait1() {
    asm volatile("cp.async.wait_group 1;");
}
__device__ __forceinline__ u64 pack2(float lo, float hi) {
    u64 r; asm("mov.b64 %0, {%1, %2};" : "=l"(r) : "f"(lo), "f"(hi)); return r;
}
__device__ __forceinline__ void fma2(u64& d, u64 a, u64 b) {
    asm("fma.rn.f32x2 %0, %1, %2, %0;" : "+l"(d) : "l"(a), "l"(b));
}

__global__ __launch_bounds__(THREADS, 2)
void kron_kernel(const float4* __restrict__ gx,
                 float4*       __restrict__ gout,
                 const float*  __restrict__ f1,
                 const float*  __restrict__ f2,
                 const float*  __restrict__ bias,
                 long long nrows)
{
    extern __shared__ float4 dbuf[];          // 2 * BUF_F4 float4
    __shared__ u64 f1t[64];                   // [i*8+k] = (f1[i,k], f1[i,k])
    __shared__ u64 g2t[32];                   // [l*4+p] = (f2[2p,l], f2[2p+1,l])
    __shared__ u64 bt[32];                    // bias as packed pairs

    const int tid = threadIdx.x;
    if (tid < 32) {
        int l = tid >> 2, p = tid & 3;
        g2t[tid] = pack2(f2[(2 * p) * 8 + l], f2[(2 * p + 1) * 8 + l]);
        bt[tid]  = pack2(bias[2 * tid], bias[2 * tid + 1]);
    }
    if (tid < 64) f1t[tid] = pack2(f1[tid], f1[tid]);
    __syncthreads();

    // f2-pair table lives in registers for the whole kernel (tile-invariant)
    u64 g2r[32];
    #pragma unroll
    for (int m = 0; m < 32; m++) g2r[m] = g2t[m];

    const long long ntiles = (nrows + TILE_ROWS - 1) / TILE_ROWS;
    const uint32_t sb0 = s2u(dbuf);
    const uint32_t sb1 = s2u(dbuf + BUF_F4);

    long long tile = blockIdx.x;

    // ---- prologue: stage first tile into buffer 0 ----
    if (tile < ntiles) {
        const float4* src = gx + tile * (TILE_ROWS * 16);
        long long base = tile * TILE_ROWS;
        #pragma unroll
        for (int i = 0; i < 16; i++) {
            int f = tid + i * THREADS;
            int r = f >> 4;
            if (base + r < nrows)
                cp16(sb0 + (uint32_t)(f + r) * 16u, src + f);
        }
    }
    cp_commit();

    int b = 0;
    while (tile < ntiles) {
        const long long nt = tile + gridDim.x;

        // ---- prefetch next tile into the other buffer ----
        if (nt < ntiles) {
            const float4* src = gx + nt * (TILE_ROWS * 16);
            long long base = nt * TILE_ROWS;
            uint32_t sbn = b ? sb0 : sb1;
            #pragma unroll
            for (int i = 0; i < 16; i++) {
                int f = tid + i * THREADS;
                int r = f >> 4;
                if (base + r < nrows)
                    cp16(sbn + (uint32_t)(f + r) * 16u, src + f);
            }
        }
        cp_commit();
        cp_wait1();                 // current tile's group complete
        __syncthreads();

        // ---- compute: one thread per row, fully packed f32x2 ----
        float4* xrow = dbuf + b * BUF_F4 + tid * PITCH4;
        u64 y[32];
        #pragma unroll
        for (int m = 0; m < 32; m++) y[m] = bt[m];

        #pragma unroll 1
        for (int k = 0; k < 8; k++) {
            float4 xa = xrow[2 * k];
            float4 xb = xrow[2 * k + 1];
            float xs[8] = {xa.x, xa.y, xa.z, xa.w, xb.x, xb.y, xb.z, xb.w};
            u64 t0 = 0, t1 = 0, t2 = 0, t3 = 0;   // (0.0f, 0.0f) packed
            #pragma unroll
            for (int l = 0; l < 8; l++) {
                u64 x2 = pack2(xs[l], xs[l]);
                fma2(t0, x2, g2r[l * 4 + 0]);
                fma2(t1, x2, g2r[l * 4 + 1]);
                fma2(t2, x2, g2r[l * 4 + 2]);
                fma2(t3, x2, g2r[l * 4 + 3]);
            }
            #pragma unroll
            for (int i = 0; i < 8; i++) {
                u64 a2 = f1t[i * 8 + k];          // broadcast LDS.64
                fma2(y[i * 4 + 0], a2, t0);
                fma2(y[i * 4 + 1], a2, t1);
                fma2(y[i * 4 + 2], a2, t2);
                fma2(y[i * 4 + 3], a2, t3);
            }
        }

        // write result into own row slot (in place; own-row only)
        {
            ulonglong2* yr = (ulonglong2*)xrow;
            #pragma unroll
            for (int i = 0; i < 8; i++) {
                yr[2 * i]     = make_ulonglong2(y[i * 4 + 0], y[i * 4 + 1]);
                yr[2 * i + 1] = make_ulonglong2(y[i * 4 + 2], y[i * 4 + 3]);
            }
        }
        __syncthreads();

        // ---- coalesced store ----
        {
            float4* dst = gout + tile * (TILE_ROWS * 16);
            const float4* sbuf = dbuf + b * BUF_F4;
            long long base = tile * TILE_ROWS;
            #pragma unroll
            for (int i = 0; i < 16; i++) {
                int f = tid + i * THREADS;
                int r = f >> 4;
                if (base + r < nrows)
                    dst[f] = sbuf[f + r];
            }
        }
        __syncthreads();            // buffer b reused by next iteration's prefetch

        tile = nt;
        b ^= 1;
    }
}

extern "C" void kernel_launch(void* const* d_in, const int* in_sizes, int n_in,
                              void* d_out, int out_size)
{
    const float* x    = (const float*)d_in[0];
    const float* f1   = (const float*)d_in[1];
    const float* f2   = (const float*)d_in[2];
    const float* bias = (const float*)d_in[3];
    float* out = (float*)d_out;

    long long nrows = (long long)in_sizes[0] / 64;

    const int smem_bytes = 2 * BUF_F4 * sizeof(float4);   // 69632
    cudaFuncSetAttribute(kron_kernel,
                         cudaFuncAttributeMaxDynamicSharedMemorySize, smem_bytes);

    int grid = 2 * 148;     // persistent: 2 blocks per SM
    kron_kernel<<<grid, THREADS, smem_bytes>>>(
        (const float4*)x, (float4*)out, f1, f2, bias, nrows);
}